// round 15
// baseline (speedup 1.0000x reference)
#include <cuda_runtime.h>
#include <cuda_fp16.h>
#include <cstdint>
#include <cstddef>

#define B_   2
#define S_   2048
#define DIM_ 4096
#define NH_  32
#define NKV_ 8
#define HD_  128
#define NQKV (DIM_ + 2 * NKV_ * HD_)    // 6144

// ---------------- scratch (no allocations allowed) ----------------
__device__ __half g_xh[(size_t)B_ * S_ * DIM_];        // x fp16 (hi only)
__device__ __half g_wbh[(size_t)NQKV * DIM_];          // [wq;wk;wv] transposed hi
__device__ __half g_woh[(size_t)DIM_ * DIM_];          // wo transposed hi
__device__ __half g_ah[(size_t)B_ * S_ * DIM_];        // attention out (hi only)

__device__ __half g_qsh[(size_t)B_ * S_ * NH_ * HD_];  // post-rope Q hi/lo
__device__ __half g_qsl[(size_t)B_ * S_ * NH_ * HD_];
__device__ __half g_ksh[(size_t)B_ * S_ * NKV_ * HD_];
__device__ __half g_ksl[(size_t)B_ * S_ * NKV_ * HD_];
__device__ __half g_vth[(size_t)B_ * NKV_ * HD_ * S_]; // V^T [b][kv][d][s] hi/lo
__device__ __half g_vtl[(size_t)B_ * NKV_ * HD_ * S_];

// ============================ PTX helpers (sm_80-portable) ============================
__device__ __forceinline__ uint32_t smem_u32(const void* p) {
    uint32_t a;
    asm("{ .reg .u64 t; cvta.to.shared.u64 t, %1; cvt.u32.u64 %0, t; }"
        : "=r"(a) : "l"(p));
    return a;
}

__device__ __forceinline__ void cp16(uint32_t dst, const void* src) {
    asm volatile("cp.async.cg.shared.global [%0], [%1], 16;" :: "r"(dst), "l"(src));
}

__device__ __forceinline__ void ldmx4(uint32_t* r, uint32_t addr) {
    asm volatile("ldmatrix.sync.aligned.m8n8.x4.shared.b16 {%0,%1,%2,%3}, [%4];"
        : "=r"(r[0]), "=r"(r[1]), "=r"(r[2]), "=r"(r[3]) : "r"(addr));
}

#define CP_COMMIT() asm volatile("cp.async.commit_group;" ::: "memory")
#define CP_WAIT1()  asm volatile("cp.async.wait_group 1;"  ::: "memory")
#define CP_WAIT0()  asm volatile("cp.async.wait_group 0;"  ::: "memory")

#define MMA_F16(c, A, Bf)                                                         \
    asm volatile(                                                                 \
        "mma.sync.aligned.m16n8k16.row.col.f32.f16.f16.f32 "                      \
        "{%0,%1,%2,%3},{%4,%5,%6,%7},{%8,%9},{%0,%1,%2,%3};"                      \
        : "+f"((c)[0]), "+f"((c)[1]), "+f"((c)[2]), "+f"((c)[3])                  \
        : "r"((A)[0]), "r"((A)[1]), "r"((A)[2]), "r"((A)[3]),                     \
          "r"((Bf)[0]), "r"((Bf)[1]))

#define MMA_F16S(c, A, b0, b1)                                                    \
    asm volatile(                                                                 \
        "mma.sync.aligned.m16n8k16.row.col.f32.f16.f16.f32 "                      \
        "{%0,%1,%2,%3},{%4,%5,%6,%7},{%8,%9},{%0,%1,%2,%3};"                      \
        : "+f"((c)[0]), "+f"((c)[1]), "+f"((c)[2]), "+f"((c)[3])                  \
        : "r"((A)[0]), "r"((A)[1]), "r"((A)[2]), "r"((A)[3]),                     \
          "r"(b0), "r"(b1))

// f16-accumulator MMA (2x rate) — used only for residual-correction passes.
#define MMA_H16(c, A, b0, b1)                                                     \
    asm volatile(                                                                 \
        "mma.sync.aligned.m16n8k16.row.col.f16.f16.f16.f16 "                      \
        "{%0,%1},{%2,%3,%4,%5},{%6,%7},{%0,%1};"                                  \
        : "+r"((c)[0]), "+r"((c)[1])                                              \
        : "r"((A)[0]), "r"((A)[1]), "r"((A)[2]), "r"((A)[3]),                     \
          "r"(b0), "r"(b1))

// ============================================================================
// GEMM mainloop: C fp32 = Ah @ Bh^T  (single-pass fp16, weights hi-only)
// CTA 128x128, BK=64, 8 warps 2x4, ldmatrix, 2 CTAs/SM, 3-stage pipeline.
// ============================================================================
#define TILE_B   18432          // 128 x 144
#define STAGE_B  (2 * TILE_B)   // 36864

struct GemmCore {
    uint32_t sm0;
    int tid, lane, wid, wm, wn, q, rb;
    int row0, col0;
    const __half* src_[2];
    int K;

    __device__ __forceinline__ void init(char* sm,
        const __half* Ah, const __half* Bh, int K_) {
        sm0 = smem_u32(sm);
        tid = threadIdx.x; lane = tid & 31; wid = tid >> 5;
        wm = wid >> 2; wn = wid & 3; q = lane & 3; rb = lane >> 2;
        row0 = blockIdx.y * 128; col0 = blockIdx.x * 128;
        K = K_;
        src_[0] = Ah + (size_t)row0 * K;
        src_[1] = Bh + (size_t)col0 * K;
    }

    __device__ __forceinline__ void load_stage(int it, int s) {
        const uint32_t base = sm0 + s * STAGE_B;
        const int kel = it * 64;
#pragma unroll
        for (int t = 0; t < 2; ++t) {
            const __half* g = src_[t] + kel;
#pragma unroll
            for (int i = 0; i < 4; ++i) {
                int idx = tid + i * 256;
                int r = idx >> 3, kc = idx & 7;
                cp16(base + t * TILE_B + r * 144 + kc * 16,
                     g + (size_t)r * K + kc * 8);
            }
        }
        CP_COMMIT();
    }

    __device__ __forceinline__ void mainloop(float acc[4][4][4]) {
#pragma unroll
        for (int i = 0; i < 4; ++i)
#pragma unroll
            for (int j = 0; j < 4; ++j)
#pragma unroll
                for (int u = 0; u < 4; ++u) acc[i][j][u] = 0.f;

        const int KIT = K >> 6;
        load_stage(0, 0);
        load_stage(1, 1);

        const int a_row = lane & 15;
        const int a_off = (lane >> 4) * 16;
        const int b_row = (lane & 7) + (lane >> 4) * 8;
        const int b_off = ((lane >> 3) & 1) * 16;

        int cur = 0, nxt = 2;
        for (int it = 0; it < KIT; ++it) {
            if (it + 1 < KIT) { CP_WAIT1(); }
            else              { CP_WAIT0(); }
            __syncthreads();
            if (it + 2 < KIT) load_stage(it + 2, nxt);

            const uint32_t base = sm0 + cur * STAGE_B;
#pragma unroll
            for (int kk = 0; kk < 4; ++kk) {
                const int kb = kk * 32;
                uint32_t ah[4][4], bh[4][2];
#pragma unroll
                for (int mf = 0; mf < 4; ++mf)
                    ldmx4(ah[mf], base + (wm * 64 + mf * 16 + a_row) * 144 + kb + a_off);
#pragma unroll
                for (int np = 0; np < 2; ++np) {
                    uint32_t t4[4];
                    ldmx4(t4, base + TILE_B +
                              (wn * 32 + np * 16 + b_row) * 144 + kb + b_off);
                    bh[2*np][0] = t4[0]; bh[2*np][1] = t4[1];
                    bh[2*np+1][0] = t4[2]; bh[2*np+1][1] = t4[3];
                }
#pragma unroll
                for (int mf = 0; mf < 4; ++mf)
#pragma unroll
                    for (int nf = 0; nf < 4; ++nf)
                        MMA_F16(acc[mf][nf], ah[mf], bh[nf]);
            }
            cur = (cur == 2) ? 0 : cur + 1;
            nxt = (nxt == 2) ? 0 : nxt + 1;
        }
    }
};

// ---- RoPE + scale + fp16 hi/lo split epilogue (shared) ----
__device__ __forceinline__ void rope_epilogue(
    float acc[4][4][4], const GemmCore& gc, int colbase,
    const float* __restrict__ cs, const float* __restrict__ sn,
    __half* __restrict__ Oh, __half* __restrict__ Ol, int Nout, float scale)
{
#pragma unroll
    for (int mf = 0; mf < 4; ++mf) {
        int row = gc.row0 + gc.wm * 64 + mf * 16 + gc.rb;
        int s0 = row & (S_ - 1);
#pragma unroll
        for (int nf = 0; nf < 4; ++nf) {
            int col = colbase + gc.wn * 32 + nf * 8 + gc.q * 2;
            int p = (col & (HD_ - 1)) >> 1;
#pragma unroll
            for (int half = 0; half < 2; ++half) {
                int s = s0 + half * 8;
                float c = cs[(s << 6) + p];
                float si = sn[(s << 6) + p];
                float xr = acc[mf][nf][2 * half];
                float xi = acc[mf][nf][2 * half + 1];
                float o0 = fmaf(xr, c, -xi * si) * scale;
                float o1 = fmaf(xr, si,  xi * c) * scale;
                __half h0 = __float2half_rn(o0);
                __half h1 = __float2half_rn(o1);
                size_t off = (size_t)(row + half * 8) * Nout + col;
                *(__half2*)(Oh + off) = __halves2half2(h0, h1);
                *(__half2*)(Ol + off) = __halves2half2(
                    __float2half_rn(o0 - __half2float(h0)),
                    __float2half_rn(o1 - __half2float(h1)));
            }
        }
    }
}

// ---- fused QKV projection: one GEMM over [6144,4096] weights ----
__global__ __launch_bounds__(256, 2) void gemm_qkv(
    const __half* __restrict__ Ah, const __half* __restrict__ Bh,
    const float* __restrict__ cs, const float* __restrict__ sn,
    __half* __restrict__ qsh, __half* __restrict__ qsl,
    __half* __restrict__ ksh, __half* __restrict__ ksl,
    __half* __restrict__ vth, __half* __restrict__ vtl)
{
    extern __shared__ __align__(16) char sm[];
    GemmCore gc; gc.init(sm, Ah, Bh, DIM_);
    float acc[4][4][4];
    gc.mainloop(acc);

    if (gc.col0 < DIM_) {
        rope_epilogue(acc, gc, gc.col0, cs, sn, qsh, qsl, DIM_,
                      0.08838834764831845f);
    } else if (gc.col0 < DIM_ + NKV_ * HD_) {
        rope_epilogue(acc, gc, gc.col0 - DIM_, cs, sn, ksh, ksl, NKV_ * HD_, 1.0f);
    } else {
        const int colbase = gc.col0 - (DIM_ + NKV_ * HD_);
#pragma unroll
        for (int mf = 0; mf < 4; ++mf) {
            int row = gc.row0 + gc.wm * 64 + mf * 16 + gc.rb;
            int b = row >> 11;
            int s = row & (S_ - 1);
#pragma unroll
            for (int nf = 0; nf < 4; ++nf) {
                int col = colbase + gc.wn * 32 + nf * 8 + gc.q * 2;
                int kv = col >> 7;
                int d  = col & (HD_ - 1);
                size_t base = ((size_t)(b * NKV_ + kv) * HD_ + d) * S_;
#pragma unroll
                for (int half = 0; half < 2; ++half) {
                    int ss = s + half * 8;
#pragma unroll
                    for (int e = 0; e < 2; ++e) {
                        float v = acc[mf][nf][2 * half + e];
                        __half hi = __float2half_rn(v);
                        size_t off = base + (size_t)e * S_ + ss;
                        vth[off] = hi;
                        vtl[off] = __float2half_rn(v - __half2float(hi));
                    }
                }
            }
        }
    }
}

// ---- plain GEMM: fp32 output (O projection) ----
__global__ __launch_bounds__(256, 2) void gemm_mma(
    const __half* __restrict__ Ah, const __half* __restrict__ Bh,
    float* __restrict__ C, int M, int N, int K)
{
    extern __shared__ __align__(16) char sm[];
    GemmCore gc; gc.init(sm, Ah, Bh, K);
    float acc[4][4][4];
    gc.mainloop(acc);
#pragma unroll
    for (int mf = 0; mf < 4; ++mf) {
        int row = gc.row0 + gc.wm * 64 + mf * 16 + gc.rb;
#pragma unroll
        for (int nf = 0; nf < 4; ++nf) {
            int col = gc.col0 + gc.wn * 32 + nf * 8 + gc.q * 2;
            *(float2*)(C + (size_t)row * N + col) =
                make_float2(acc[mf][nf][0], acc[mf][nf][1]);
            *(float2*)(C + (size_t)(row + 8) * N + col) =
                make_float2(acc[mf][nf][2], acc[mf][nf][3]);
        }
    }
}

// ============================================================================
// Fused prep: z=0 wq, z=1 wk, z=2 wv (combined buffer), z=3 wo, z=4 x->fp16
// ============================================================================
__global__ __launch_bounds__(256) void prep_all(
    const float* __restrict__ x,
    const float* __restrict__ wq, const float* __restrict__ wk,
    const float* __restrict__ wv, const float* __restrict__ wo,
    __half* __restrict__ xh,
    __half* __restrict__ wbh, __half* __restrict__ woh)
{
    const int z = blockIdx.z;
    const int tx = threadIdx.x, ty = threadIdx.y;

    if (z == 4) {
        int i = (blockIdx.y * 128 + blockIdx.x) * 256 + ty * 32 + tx;
        float4 v = ((const float4*)x)[i];
        ((__half2*)xh)[2 * i + 0] = __floats2half2_rn(v.x, v.y);
        ((__half2*)xh)[2 * i + 1] = __floats2half2_rn(v.z, v.w);
        return;
    }

    const float* w; __half* th; int N; int rowbase;
    switch (z) {
        case 0: w = wq; th = wbh; N = DIM_;        rowbase = 0;     break;
        case 1: w = wk; th = wbh; N = NKV_ * HD_;  rowbase = DIM_;  break;
        case 2: w = wv; th = wbh; N = NKV_ * HD_;  rowbase = DIM_ + NKV_ * HD_; break;
        default: w = wo; th = woh; N = DIM_;       rowbase = 0;     break;
    }
    const int K = DIM_;
    int n0 = blockIdx.x * 32, k0 = blockIdx.y * 32;
    if (n0 >= N) return;

    __shared__ float s[32][33];
#pragma unroll
    for (int i = ty; i < 32; i += 8)
        s[i][tx] = w[(size_t)(k0 + i) * N + n0 + tx];
    __syncthreads();
#pragma unroll
    for (int i = ty; i < 32; i += 8)
        th[(size_t)(rowbase + n0 + i) * K + k0 + tx] = __float2half_rn(s[tx][i]);
}

// ============================================================================
// Tensor-core flash attention.
// Main passes (Qh·Kh, Ph·Vh): f32 accumulation.
// Residual passes (Qh·Kl, Ql·Kh, Ph·Vl): f16 accumulation (2x rate),
// folded into the f32 accumulators once per k-block.
// ============================================================================
#define AK       64
#define NKB      (S_ / AK)
#define KSTRIDE  272
#define VSTRIDE  144
#define OFF_KL   17408
#define OFF_VH   34816
#define OFF_VL   53248
#define STG      71680

__global__ __launch_bounds__(256, 1) void attn_mma(
    const __half* __restrict__ Qh, const __half* __restrict__ Ql,
    const __half* __restrict__ Kh, const __half* __restrict__ Kl,
    const __half* __restrict__ Vh, const __half* __restrict__ Vl,
    __half* __restrict__ Oh)
{
    extern __shared__ __align__(16) char sm[];
    const uint32_t sm0 = smem_u32(sm);
    const int tid = threadIdx.x, lane = tid & 31, w = tid >> 5;
    const int g = lane >> 2, q = lane & 3;
    const int q0 = blockIdx.x * 128;
    const int h = blockIdx.y, b = blockIdx.z;
    const int kvh = h >> 2;

    const int rowlane = lane & 7;
    const int part = lane >> 3;
    const int poff16 = (part & 1) * 16;
    const int plo = part >> 1;

    // ---- stage Q through smem, build register fragments ----
    uint32_t fqh[8][4], fql[8][4];
    {
        const __half* srcs[2] = { Qh, Ql };
#pragma unroll
        for (int rep = 0; rep < 2; ++rep) {
#pragma unroll
            for (int i = 0; i < 8; ++i) {
                int c = tid + i * 256;
                int r = c >> 4, cc = c & 15;
                cp16(sm0 + r * KSTRIDE + cc * 16,
                     srcs[rep] + ((size_t)((b * S_ + q0 + r) * NH_) + h) * HD_ + cc * 8);
            }
            CP_COMMIT(); CP_WAIT0();
            __syncthreads();
            uint32_t base = sm0 + (w * 16 + (lane & 15)) * KSTRIDE + (lane >> 4) * 16;
#pragma unroll
            for (int t = 0; t < 8; ++t)
                ldmx4(rep ? fql[t] : fqh[t], base + t * 32);
            __syncthreads();
        }
    }

    auto prefetch = [&](int kb, int s) {
        uint32_t st = sm0 + s * STG;
#pragma unroll
        for (int i = 0; i < 4; ++i) {
            int c = tid + i * 256;
            int r = c >> 4, cc = c & 15;
            size_t go = ((size_t)((b * S_ + kb * AK + r) * NKV_) + kvh) * HD_ + cc * 8;
            cp16(st + r * KSTRIDE + cc * 16, Kh + go);
            cp16(st + OFF_KL + r * KSTRIDE + cc * 16, Kl + go);
        }
#pragma unroll
        for (int i = 0; i < 4; ++i) {
            int c = tid + i * 256;
            int d = c >> 3, cc = c & 7;
            size_t go = ((size_t)(b * NKV_ + kvh) * HD_ + d) * S_ + kb * AK + cc * 8;
            cp16(st + OFF_VH + d * VSTRIDE + cc * 16, Vh + go);
            cp16(st + OFF_VL + d * VSTRIDE + cc * 16, Vl + go);
        }
        CP_COMMIT();
    };

    float oacc[16][4];
#pragma unroll
    for (int i = 0; i < 16; ++i)
#pragma unroll
        for (int u = 0; u < 4; ++u) oacc[i][u] = 0.f;
    float m0 = -1e30f, m1 = -1e30f, l0 = 0.f, l1 = 0.f;

    prefetch(0, 0);

    for (int kb = 0; kb < NKB; ++kb) {
        const int s = kb & 1;
        if (kb + 1 < NKB) { prefetch(kb + 1, s ^ 1); CP_WAIT1(); }
        else              { CP_WAIT0(); }
        __syncthreads();

        const uint32_t st = sm0 + s * STG;

        // ---- S = Q K^T : main f32 pass + f16-acc corrections ----
        float sacc[8][4];
        uint32_t scorr[8][2];
#pragma unroll
        for (int n = 0; n < 8; ++n) {
#pragma unroll
            for (int u = 0; u < 4; ++u) sacc[n][u] = 0.f;
            scorr[n][0] = 0; scorr[n][1] = 0;
        }

#pragma unroll
        for (int t = 0; t < 8; ++t) {
#pragma unroll
            for (int n = 0; n < 8; ++n) {
                uint32_t r4[4];
                ldmx4(r4, st + (n * 8 + rowlane) * KSTRIDE + t * 32 + poff16 +
                          plo * OFF_KL);
                MMA_F16S(sacc[n], fqh[t], r4[0], r4[1]);     // Qh*Kh (f32)
                MMA_H16(scorr[n], fqh[t], r4[2], r4[3]);     // Qh*Kl (f16)
                MMA_H16(scorr[n], fql[t], r4[0], r4[1]);     // Ql*Kh (f16)
            }
        }
        // fold corrections
#pragma unroll
        for (int n = 0; n < 8; ++n) {
            __half2 c0 = *(__half2*)&scorr[n][0];
            __half2 c1 = *(__half2*)&scorr[n][1];
            sacc[n][0] += __low2float(c0);  sacc[n][1] += __high2float(c0);
            sacc[n][2] += __low2float(c1);  sacc[n][3] += __high2float(c1);
        }

        // ---- online softmax ----
        float rmax0 = -1e30f, rmax1 = -1e30f;
#pragma unroll
        for (int n = 0; n < 8; ++n) {
            rmax0 = fmaxf(rmax0, fmaxf(sacc[n][0], sacc[n][1]));
            rmax1 = fmaxf(rmax1, fmaxf(sacc[n][2], sacc[n][3]));
        }
        rmax0 = fmaxf(rmax0, __shfl_xor_sync(0xffffffffu, rmax0, 1));
        rmax0 = fmaxf(rmax0, __shfl_xor_sync(0xffffffffu, rmax0, 2));
        rmax1 = fmaxf(rmax1, __shfl_xor_sync(0xffffffffu, rmax1, 1));
        rmax1 = fmaxf(rmax1, __shfl_xor_sync(0xffffffffu, rmax1, 2));

        float nm0 = fmaxf(m0, rmax0), nm1 = fmaxf(m1, rmax1);
        float f0 = __expf(m0 - nm0),  f1 = __expf(m1 - nm1);
        m0 = nm0; m1 = nm1;

        float sum0 = 0.f, sum1 = 0.f;
#pragma unroll
        for (int n = 0; n < 8; ++n) {
            float p0 = __expf(sacc[n][0] - nm0);
            float p1 = __expf(sacc[n][1] - nm0);
            float p2 = __expf(sacc[n][2] - nm1);
            float p3 = __expf(sacc[n][3] - nm1);
            sum0 += p0 + p1; sum1 += p2 + p3;
            sacc[n][0] = p0; sacc[n][1] = p1; sacc[n][2] = p2; sacc[n][3] = p3;
        }
        sum0 += __shfl_xor_sync(0xffffffffu, sum0, 1);
        sum0 += __shfl_xor_sync(0xffffffffu, sum0, 2);
        sum1 += __shfl_xor_sync(0xffffffffu, sum1, 1);
        sum1 += __shfl_xor_sync(0xffffffffu, sum1, 2);
        l0 = l0 * f0 + sum0;
        l1 = l1 * f1 + sum1;

        // P -> hi A fragments (register repack)
        uint32_t pah[4][4];
#pragma unroll
        for (int t = 0; t < 4; ++t) {
#pragma unroll
            for (int hw = 0; hw < 2; ++hw) {
                const float* pv = sacc[2 * t + hw];
#pragma unroll
                for (int uu = 0; uu < 2; ++uu) {
                    __half2 hp = __floats2half2_rn(pv[2 * uu], pv[2 * uu + 1]);
                    pah[t][hw * 2 + uu] = *(uint32_t*)&hp;
                }
            }
        }

#pragma unroll
        for (int nf = 0; nf < 16; ++nf) {
            oacc[nf][0] *= f0; oacc[nf][1] *= f0;
            oacc[nf][2] *= f1; oacc[nf][3] *= f1;
        }

        // ---- O += Ph*Vh (f32) + Ph*Vl (f16 corr) ----
        uint32_t ocorr[16][2];
#pragma unroll
        for (int nf = 0; nf < 16; ++nf) { ocorr[nf][0] = 0; ocorr[nf][1] = 0; }

#pragma unroll
        for (int t = 0; t < 4; ++t) {
#pragma unroll
            for (int nf = 0; nf < 16; ++nf) {
                uint32_t r4[4];
                ldmx4(r4, st + OFF_VH + (nf * 8 + rowlane) * VSTRIDE + t * 32 +
                          poff16 + plo * (OFF_VL - OFF_VH));
                MMA_F16S(oacc[nf], pah[t], r4[0], r4[1]);    // Ph*Vh (f32)
                MMA_H16(ocorr[nf], pah[t], r4[2], r4[3]);    // Ph*Vl (f16)
            }
        }
#pragma unroll
        for (int nf = 0; nf < 16; ++nf) {
            __half2 c0 = *(__half2*)&ocorr[nf][0];
            __half2 c1 = *(__half2*)&ocorr[nf][1];
            oacc[nf][0] += __low2float(c0);  oacc[nf][1] += __high2float(c0);
            oacc[nf][2] += __low2float(c1);  oacc[nf][3] += __high2float(c1);
        }
        __syncthreads();
    }

    // ---- epilogue: normalize, store fp16 hi only ----
    float inv0 = 1.0f / l0, inv1 = 1.0f / l1;
    int r0 = q0 + w * 16 + g;
#pragma unroll
    for (int nf = 0; nf < 16; ++nf) {
        int col = nf * 8 + 2 * q;
        {
            size_t off = (size_t)(b * S_ + r0) * DIM_ + h * HD_ + col;
            *(__half2*)(Oh + off) =
                __floats2half2_rn(oacc[nf][0] * inv0, oacc[nf][1] * inv0);
        }
        {
            size_t off = (size_t)(b * S_ + r0 + 8) * DIM_ + h * HD_ + col;
            *(__half2*)(Oh + off) =
                __floats2half2_rn(oacc[nf][2] * inv1, oacc[nf][3] * inv1);
        }
    }
}

// ============================================================================
// launch
// ============================================================================
extern "C" void kernel_launch(void* const* d_in, const int* in_sizes, int n_in,
                              void* d_out, int out_size)
{
    const float* x  = (const float*)d_in[0];
    const float* wq = (const float*)d_in[1];
    const float* wk = (const float*)d_in[2];
    const float* wv = (const float*)d_in[3];
    const float* wo = (const float*)d_in[4];
    const float* fc = (const float*)d_in[5];
    const float* fs = (const float*)d_in[6];
    float* out = (float*)d_out;

    __half *xh, *wbh, *woh, *ah;
    __half *qsh, *qsl, *ksh, *ksl, *vth, *vtl;
    cudaGetSymbolAddress((void**)&xh, g_xh);
    cudaGetSymbolAddress((void**)&wbh, g_wbh);
    cudaGetSymbolAddress((void**)&woh, g_woh);
    cudaGetSymbolAddress((void**)&ah, g_ah);
    cudaGetSymbolAddress((void**)&qsh, g_qsh); cudaGetSymbolAddress((void**)&qsl, g_qsl);
    cudaGetSymbolAddress((void**)&ksh, g_ksh); cudaGetSymbolAddress((void**)&ksl, g_ksl);
    cudaGetSymbolAddress((void**)&vth, g_vth); cudaGetSymbolAddress((void**)&vtl, g_vtl);

    const int GEMM_SMEM = 3 * STAGE_B;   // 110592
    cudaFuncSetAttribute(gemm_qkv, cudaFuncAttributeMaxDynamicSharedMemorySize,
                         GEMM_SMEM);
    cudaFuncSetAttribute(gemm_mma, cudaFuncAttributeMaxDynamicSharedMemorySize,
                         GEMM_SMEM);
    const int ATTN_SMEM = 2 * STG;       // 143360
    cudaFuncSetAttribute(attn_mma, cudaFuncAttributeMaxDynamicSharedMemorySize,
                         ATTN_SMEM);

    const int M = B_ * S_;               // 4096

    prep_all<<<dim3(128, 128, 5), dim3(32, 8)>>>(
        x, wq, wk, wv, wo, xh, wbh, woh);

    gemm_qkv<<<dim3(NQKV / 128, M / 128), 256, GEMM_SMEM>>>(
        xh, wbh, fc, fs, qsh, qsl, ksh, ksl, vth, vtl);

    attn_mma<<<dim3(S_ / 128, NH_, B_), 256, ATTN_SMEM>>>(
        qsh, qsl, ksh, ksl, vth, vtl, ah);

    gemm_mma<<<dim3(DIM_ / 128, M / 128), 256, GEMM_SMEM>>>(
        ah, woh, out, M, DIM_, DIM_);
}

// round 16
// speedup vs baseline: 1.0549x; 1.0549x over previous
#include <cuda_runtime.h>
#include <cuda_fp16.h>
#include <cstdint>
#include <cstddef>

#define B_   2
#define S_   2048
#define DIM_ 4096
#define NH_  32
#define NKV_ 8
#define HD_  128
#define NQKV (DIM_ + 2 * NKV_ * HD_)    // 6144

// ---------------- scratch (no allocations allowed) ----------------
__device__ __half g_xh[(size_t)B_ * S_ * DIM_];        // x fp16 (hi only)
__device__ __half g_wbh[(size_t)NQKV * DIM_];          // [wq;wk;wv] transposed hi
__device__ __half g_woh[(size_t)DIM_ * DIM_];          // wo transposed hi
__device__ __half g_ah[(size_t)B_ * S_ * DIM_];        // attention out (hi only)

__device__ __half g_qsh[(size_t)B_ * S_ * NH_ * HD_];  // post-rope Q hi/lo
__device__ __half g_qsl[(size_t)B_ * S_ * NH_ * HD_];
__device__ __half g_ksh[(size_t)B_ * S_ * NKV_ * HD_];
__device__ __half g_ksl[(size_t)B_ * S_ * NKV_ * HD_];
__device__ __half g_vth[(size_t)B_ * NKV_ * HD_ * S_]; // V^T [b][kv][d][s] hi/lo
__device__ __half g_vtl[(size_t)B_ * NKV_ * HD_ * S_];

// ============================ PTX helpers (sm_80-portable) ============================
__device__ __forceinline__ uint32_t smem_u32(const void* p) {
    uint32_t a;
    asm("{ .reg .u64 t; cvta.to.shared.u64 t, %1; cvt.u32.u64 %0, t; }"
        : "=r"(a) : "l"(p));
    return a;
}

__device__ __forceinline__ void cp16(uint32_t dst, const void* src) {
    asm volatile("cp.async.cg.shared.global [%0], [%1], 16;" :: "r"(dst), "l"(src));
}

__device__ __forceinline__ void ldmx4(uint32_t* r, uint32_t addr) {
    asm volatile("ldmatrix.sync.aligned.m8n8.x4.shared.b16 {%0,%1,%2,%3}, [%4];"
        : "=r"(r[0]), "=r"(r[1]), "=r"(r[2]), "=r"(r[3]) : "r"(addr));
}

#define CP_COMMIT() asm volatile("cp.async.commit_group;" ::: "memory")
#define CP_WAIT1()  asm volatile("cp.async.wait_group 1;"  ::: "memory")
#define CP_WAIT0()  asm volatile("cp.async.wait_group 0;"  ::: "memory")

#define MMA_F16(c, A, Bf)                                                         \
    asm volatile(                                                                 \
        "mma.sync.aligned.m16n8k16.row.col.f32.f16.f16.f32 "                      \
        "{%0,%1,%2,%3},{%4,%5,%6,%7},{%8,%9},{%0,%1,%2,%3};"                      \
        : "+f"((c)[0]), "+f"((c)[1]), "+f"((c)[2]), "+f"((c)[3])                  \
        : "r"((A)[0]), "r"((A)[1]), "r"((A)[2]), "r"((A)[3]),                     \
          "r"((Bf)[0]), "r"((Bf)[1]))

#define MMA_F16S(c, A, b0, b1)                                                    \
    asm volatile(                                                                 \
        "mma.sync.aligned.m16n8k16.row.col.f32.f16.f16.f32 "                      \
        "{%0,%1,%2,%3},{%4,%5,%6,%7},{%8,%9},{%0,%1,%2,%3};"                      \
        : "+f"((c)[0]), "+f"((c)[1]), "+f"((c)[2]), "+f"((c)[3])                  \
        : "r"((A)[0]), "r"((A)[1]), "r"((A)[2]), "r"((A)[3]),                     \
          "r"(b0), "r"(b1))

// ============================================================================
// GEMM mainloop: C fp32 = Ah @ Bh^T  (single-pass fp16, weights hi-only)
// CTA 128x128, BK=64, 8 warps 2x4, ldmatrix, 2 CTAs/SM, 3-stage pipeline.
// ============================================================================
#define TILE_B   18432          // 128 x 144
#define STAGE_B  (2 * TILE_B)   // 36864

struct GemmCore {
    uint32_t sm0;
    int tid, lane, wid, wm, wn, q, rb;
    int row0, col0;
    const __half* src_[2];
    int K;

    __device__ __forceinline__ void init(char* sm,
        const __half* Ah, const __half* Bh, int K_) {
        sm0 = smem_u32(sm);
        tid = threadIdx.x; lane = tid & 31; wid = tid >> 5;
        wm = wid >> 2; wn = wid & 3; q = lane & 3; rb = lane >> 2;
        row0 = blockIdx.y * 128; col0 = blockIdx.x * 128;
        K = K_;
        src_[0] = Ah + (size_t)row0 * K;
        src_[1] = Bh + (size_t)col0 * K;
    }

    __device__ __forceinline__ void load_stage(int it, int s) {
        const uint32_t base = sm0 + s * STAGE_B;
        const int kel = it * 64;
#pragma unroll
        for (int t = 0; t < 2; ++t) {
            const __half* g = src_[t] + kel;
#pragma unroll
            for (int i = 0; i < 4; ++i) {
                int idx = tid + i * 256;
                int r = idx >> 3, kc = idx & 7;
                cp16(base + t * TILE_B + r * 144 + kc * 16,
                     g + (size_t)r * K + kc * 8);
            }
        }
        CP_COMMIT();
    }

    __device__ __forceinline__ void mainloop(float acc[4][4][4]) {
#pragma unroll
        for (int i = 0; i < 4; ++i)
#pragma unroll
            for (int j = 0; j < 4; ++j)
#pragma unroll
                for (int u = 0; u < 4; ++u) acc[i][j][u] = 0.f;

        const int KIT = K >> 6;
        load_stage(0, 0);
        load_stage(1, 1);

        const int a_row = lane & 15;
        const int a_off = (lane >> 4) * 16;
        const int b_row = (lane & 7) + (lane >> 4) * 8;
        const int b_off = ((lane >> 3) & 1) * 16;

        int cur = 0, nxt = 2;
        for (int it = 0; it < KIT; ++it) {
            if (it + 1 < KIT) { CP_WAIT1(); }
            else              { CP_WAIT0(); }
            __syncthreads();
            if (it + 2 < KIT) load_stage(it + 2, nxt);

            const uint32_t base = sm0 + cur * STAGE_B;
#pragma unroll
            for (int kk = 0; kk < 4; ++kk) {
                const int kb = kk * 32;
                uint32_t ah[4][4], bh[4][2];
#pragma unroll
                for (int mf = 0; mf < 4; ++mf)
                    ldmx4(ah[mf], base + (wm * 64 + mf * 16 + a_row) * 144 + kb + a_off);
#pragma unroll
                for (int np = 0; np < 2; ++np) {
                    uint32_t t4[4];
                    ldmx4(t4, base + TILE_B +
                              (wn * 32 + np * 16 + b_row) * 144 + kb + b_off);
                    bh[2*np][0] = t4[0]; bh[2*np][1] = t4[1];
                    bh[2*np+1][0] = t4[2]; bh[2*np+1][1] = t4[3];
                }
#pragma unroll
                for (int mf = 0; mf < 4; ++mf)
#pragma unroll
                    for (int nf = 0; nf < 4; ++nf)
                        MMA_F16(acc[mf][nf], ah[mf], bh[nf]);
            }
            cur = (cur == 2) ? 0 : cur + 1;
            nxt = (nxt == 2) ? 0 : nxt + 1;
        }
    }
};

// ---- RoPE + scale + fp16 hi/lo split epilogue (shared) ----
__device__ __forceinline__ void rope_epilogue(
    float acc[4][4][4], const GemmCore& gc, int colbase,
    const float* __restrict__ cs, const float* __restrict__ sn,
    __half* __restrict__ Oh, __half* __restrict__ Ol, int Nout, float scale)
{
#pragma unroll
    for (int mf = 0; mf < 4; ++mf) {
        int row = gc.row0 + gc.wm * 64 + mf * 16 + gc.rb;
        int s0 = row & (S_ - 1);
#pragma unroll
        for (int nf = 0; nf < 4; ++nf) {
            int col = colbase + gc.wn * 32 + nf * 8 + gc.q * 2;
            int p = (col & (HD_ - 1)) >> 1;
#pragma unroll
            for (int half = 0; half < 2; ++half) {
                int s = s0 + half * 8;
                float c = cs[(s << 6) + p];
                float si = sn[(s << 6) + p];
                float xr = acc[mf][nf][2 * half];
                float xi = acc[mf][nf][2 * half + 1];
                float o0 = fmaf(xr, c, -xi * si) * scale;
                float o1 = fmaf(xr, si,  xi * c) * scale;
                __half h0 = __float2half_rn(o0);
                __half h1 = __float2half_rn(o1);
                size_t off = (size_t)(row + half * 8) * Nout + col;
                *(__half2*)(Oh + off) = __halves2half2(h0, h1);
                *(__half2*)(Ol + off) = __halves2half2(
                    __float2half_rn(o0 - __half2float(h0)),
                    __float2half_rn(o1 - __half2float(h1)));
            }
        }
    }
}

// ---- fused QKV projection: one GEMM over [6144,4096] weights ----
__global__ __launch_bounds__(256, 2) void gemm_qkv(
    const __half* __restrict__ Ah, const __half* __restrict__ Bh,
    const float* __restrict__ cs, const float* __restrict__ sn,
    __half* __restrict__ qsh, __half* __restrict__ qsl,
    __half* __restrict__ ksh, __half* __restrict__ ksl,
    __half* __restrict__ vth, __half* __restrict__ vtl)
{
    extern __shared__ __align__(16) char sm[];
    GemmCore gc; gc.init(sm, Ah, Bh, DIM_);
    float acc[4][4][4];
    gc.mainloop(acc);

    if (gc.col0 < DIM_) {
        rope_epilogue(acc, gc, gc.col0, cs, sn, qsh, qsl, DIM_,
                      0.08838834764831845f);
    } else if (gc.col0 < DIM_ + NKV_ * HD_) {
        rope_epilogue(acc, gc, gc.col0 - DIM_, cs, sn, ksh, ksl, NKV_ * HD_, 1.0f);
    } else {
        const int colbase = gc.col0 - (DIM_ + NKV_ * HD_);
#pragma unroll
        for (int mf = 0; mf < 4; ++mf) {
            int row = gc.row0 + gc.wm * 64 + mf * 16 + gc.rb;
            int b = row >> 11;
            int s = row & (S_ - 1);
#pragma unroll
            for (int nf = 0; nf < 4; ++nf) {
                int col = colbase + gc.wn * 32 + nf * 8 + gc.q * 2;
                int kv = col >> 7;
                int d  = col & (HD_ - 1);
                size_t base = ((size_t)(b * NKV_ + kv) * HD_ + d) * S_;
#pragma unroll
                for (int half = 0; half < 2; ++half) {
                    int ss = s + half * 8;
#pragma unroll
                    for (int e = 0; e < 2; ++e) {
                        float v = acc[mf][nf][2 * half + e];
                        __half hi = __float2half_rn(v);
                        size_t off = base + (size_t)e * S_ + ss;
                        vth[off] = hi;
                        vtl[off] = __float2half_rn(v - __half2float(hi));
                    }
                }
            }
        }
    }
}

// ---- plain GEMM: fp32 output (O projection) ----
__global__ __launch_bounds__(256, 2) void gemm_mma(
    const __half* __restrict__ Ah, const __half* __restrict__ Bh,
    float* __restrict__ C, int M, int N, int K)
{
    extern __shared__ __align__(16) char sm[];
    GemmCore gc; gc.init(sm, Ah, Bh, K);
    float acc[4][4][4];
    gc.mainloop(acc);
#pragma unroll
    for (int mf = 0; mf < 4; ++mf) {
        int row = gc.row0 + gc.wm * 64 + mf * 16 + gc.rb;
#pragma unroll
        for (int nf = 0; nf < 4; ++nf) {
            int col = gc.col0 + gc.wn * 32 + nf * 8 + gc.q * 2;
            *(float2*)(C + (size_t)row * N + col) =
                make_float2(acc[mf][nf][0], acc[mf][nf][1]);
            *(float2*)(C + (size_t)(row + 8) * N + col) =
                make_float2(acc[mf][nf][2], acc[mf][nf][3]);
        }
    }
}

// ============================================================================
// Fused prep: z=0 wq, z=1 wk, z=2 wv (combined buffer), z=3 wo, z=4 x->fp16
// ============================================================================
__global__ __launch_bounds__(256) void prep_all(
    const float* __restrict__ x,
    const float* __restrict__ wq, const float* __restrict__ wk,
    const float* __restrict__ wv, const float* __restrict__ wo,
    __half* __restrict__ xh,
    __half* __restrict__ wbh, __half* __restrict__ woh)
{
    const int z = blockIdx.z;
    const int tx = threadIdx.x, ty = threadIdx.y;

    if (z == 4) {
        int i = (blockIdx.y * 128 + blockIdx.x) * 256 + ty * 32 + tx;
        float4 v = ((const float4*)x)[i];
        ((__half2*)xh)[2 * i + 0] = __floats2half2_rn(v.x, v.y);
        ((__half2*)xh)[2 * i + 1] = __floats2half2_rn(v.z, v.w);
        return;
    }

    const float* w; __half* th; int N; int rowbase;
    switch (z) {
        case 0: w = wq; th = wbh; N = DIM_;        rowbase = 0;     break;
        case 1: w = wk; th = wbh; N = NKV_ * HD_;  rowbase = DIM_;  break;
        case 2: w = wv; th = wbh; N = NKV_ * HD_;  rowbase = DIM_ + NKV_ * HD_; break;
        default: w = wo; th = woh; N = DIM_;       rowbase = 0;     break;
    }
    const int K = DIM_;
    int n0 = blockIdx.x * 32, k0 = blockIdx.y * 32;
    if (n0 >= N) return;

    __shared__ float s[32][33];
#pragma unroll
    for (int i = ty; i < 32; i += 8)
        s[i][tx] = w[(size_t)(k0 + i) * N + n0 + tx];
    __syncthreads();
#pragma unroll
    for (int i = ty; i < 32; i += 8)
        th[(size_t)(rowbase + n0 + i) * K + k0 + tx] = __float2half_rn(s[tx][i]);
}

// ============================================================================
// Tensor-core flash attention (fp16, 3-pass QK, 2-pass PV, ldmatrix).
// 3-stage cp.async pipeline, single __syncthreads per k-block.
// smem: 3 x 71680 = 215040 bytes.
// ============================================================================
#define AK       64
#define NKB      (S_ / AK)
#define KSTRIDE  272
#define VSTRIDE  144
#define OFF_KL   17408
#define OFF_VH   34816
#define OFF_VL   53248
#define STG      71680

__global__ __launch_bounds__(256, 1) void attn_mma(
    const __half* __restrict__ Qh, const __half* __restrict__ Ql,
    const __half* __restrict__ Kh, const __half* __restrict__ Kl,
    const __half* __restrict__ Vh, const __half* __restrict__ Vl,
    __half* __restrict__ Oh)
{
    extern __shared__ __align__(16) char sm[];
    const uint32_t sm0 = smem_u32(sm);
    const int tid = threadIdx.x, lane = tid & 31, w = tid >> 5;
    const int g = lane >> 2, q = lane & 3;
    const int q0 = blockIdx.x * 128;
    const int h = blockIdx.y, b = blockIdx.z;
    const int kvh = h >> 2;

    const int rowlane = lane & 7;
    const int part = lane >> 3;
    const int poff16 = (part & 1) * 16;
    const int plo = part >> 1;

    // ---- stage Q through smem, build register fragments ----
    uint32_t fqh[8][4], fql[8][4];
    {
        const __half* srcs[2] = { Qh, Ql };
#pragma unroll
        for (int rep = 0; rep < 2; ++rep) {
#pragma unroll
            for (int i = 0; i < 8; ++i) {
                int c = tid + i * 256;
                int r = c >> 4, cc = c & 15;
                cp16(sm0 + r * KSTRIDE + cc * 16,
                     srcs[rep] + ((size_t)((b * S_ + q0 + r) * NH_) + h) * HD_ + cc * 8);
            }
            CP_COMMIT(); CP_WAIT0();
            __syncthreads();
            uint32_t base = sm0 + (w * 16 + (lane & 15)) * KSTRIDE + (lane >> 4) * 16;
#pragma unroll
            for (int t = 0; t < 8; ++t)
                ldmx4(rep ? fql[t] : fqh[t], base + t * 32);
            __syncthreads();
        }
    }

    auto prefetch = [&](int kb, int s) {
        uint32_t st = sm0 + s * STG;
#pragma unroll
        for (int i = 0; i < 4; ++i) {
            int c = tid + i * 256;
            int r = c >> 4, cc = c & 15;
            size_t go = ((size_t)((b * S_ + kb * AK + r) * NKV_) + kvh) * HD_ + cc * 8;
            cp16(st + r * KSTRIDE + cc * 16, Kh + go);
            cp16(st + OFF_KL + r * KSTRIDE + cc * 16, Kl + go);
        }
#pragma unroll
        for (int i = 0; i < 4; ++i) {
            int c = tid + i * 256;
            int d = c >> 3, cc = c & 7;
            size_t go = ((size_t)(b * NKV_ + kvh) * HD_ + d) * S_ + kb * AK + cc * 8;
            cp16(st + OFF_VH + d * VSTRIDE + cc * 16, Vh + go);
            cp16(st + OFF_VL + d * VSTRIDE + cc * 16, Vl + go);
        }
        CP_COMMIT();
    };

    float oacc[16][4];
#pragma unroll
    for (int i = 0; i < 16; ++i)
#pragma unroll
        for (int u = 0; u < 4; ++u) oacc[i][u] = 0.f;
    float m0 = -1e30f, m1 = -1e30f, l0 = 0.f, l1 = 0.f;

    prefetch(0, 0);
    prefetch(1, 1);

    int cur = 0, nxt = 2;
    for (int kb = 0; kb < NKB; ++kb) {
        if (kb + 1 < NKB) { CP_WAIT1(); }
        else              { CP_WAIT0(); }
        __syncthreads();                       // all warps done with stage nxt's slot
        if (kb + 2 < NKB) prefetch(kb + 2, nxt);

        const uint32_t st = sm0 + cur * STG;

        // ---- S = Q K^T (3-pass split, f32 acc) ----
        float sacc[8][4];
#pragma unroll
        for (int n = 0; n < 8; ++n)
#pragma unroll
            for (int u = 0; u < 4; ++u) sacc[n][u] = 0.f;

#pragma unroll
        for (int t = 0; t < 8; ++t) {
#pragma unroll
            for (int n = 0; n < 8; ++n) {
                uint32_t r4[4];
                ldmx4(r4, st + (n * 8 + rowlane) * KSTRIDE + t * 32 + poff16 +
                          plo * OFF_KL);
                MMA_F16S(sacc[n], fqh[t], r4[0], r4[1]);
                MMA_F16S(sacc[n], fqh[t], r4[2], r4[3]);
                MMA_F16S(sacc[n], fql[t], r4[0], r4[1]);
            }
        }

        // ---- online softmax ----
        float rmax0 = -1e30f, rmax1 = -1e30f;
#pragma unroll
        for (int n = 0; n < 8; ++n) {
            rmax0 = fmaxf(rmax0, fmaxf(sacc[n][0], sacc[n][1]));
            rmax1 = fmaxf(rmax1, fmaxf(sacc[n][2], sacc[n][3]));
        }
        rmax0 = fmaxf(rmax0, __shfl_xor_sync(0xffffffffu, rmax0, 1));
        rmax0 = fmaxf(rmax0, __shfl_xor_sync(0xffffffffu, rmax0, 2));
        rmax1 = fmaxf(rmax1, __shfl_xor_sync(0xffffffffu, rmax1, 1));
        rmax1 = fmaxf(rmax1, __shfl_xor_sync(0xffffffffu, rmax1, 2));

        float nm0 = fmaxf(m0, rmax0), nm1 = fmaxf(m1, rmax1);
        float f0 = __expf(m0 - nm0),  f1 = __expf(m1 - nm1);
        m0 = nm0; m1 = nm1;

        float sum0 = 0.f, sum1 = 0.f;
#pragma unroll
        for (int n = 0; n < 8; ++n) {
            float p0 = __expf(sacc[n][0] - nm0);
            float p1 = __expf(sacc[n][1] - nm0);
            float p2 = __expf(sacc[n][2] - nm1);
            float p3 = __expf(sacc[n][3] - nm1);
            sum0 += p0 + p1; sum1 += p2 + p3;
            sacc[n][0] = p0; sacc[n][1] = p1; sacc[n][2] = p2; sacc[n][3] = p3;
        }
        sum0 += __shfl_xor_sync(0xffffffffu, sum0, 1);
        sum0 += __shfl_xor_sync(0xffffffffu, sum0, 2);
        sum1 += __shfl_xor_sync(0xffffffffu, sum1, 1);
        sum1 += __shfl_xor_sync(0xffffffffu, sum1, 2);
        l0 = l0 * f0 + sum0;
        l1 = l1 * f1 + sum1;

        // P -> hi A fragments (register repack, hi only)
        uint32_t pah[4][4];
#pragma unroll
        for (int t = 0; t < 4; ++t) {
#pragma unroll
            for (int hw = 0; hw < 2; ++hw) {
                const float* pv = sacc[2 * t + hw];
#pragma unroll
                for (int uu = 0; uu < 2; ++uu) {
                    __half2 hp = __floats2half2_rn(pv[2 * uu], pv[2 * uu + 1]);
                    pah[t][hw * 2 + uu] = *(uint32_t*)&hp;
                }
            }
        }

#pragma unroll
        for (int nf = 0; nf < 16; ++nf) {
            oacc[nf][0] *= f0; oacc[nf][1] *= f0;
            oacc[nf][2] *= f1; oacc[nf][3] *= f1;
        }

        // ---- O += Ph*(Vh+Vl)  (2-pass PV, f32 acc) ----
#pragma unroll
        for (int t = 0; t < 4; ++t) {
#pragma unroll
            for (int nf = 0; nf < 16; ++nf) {
                uint32_t r4[4];
                ldmx4(r4, st + OFF_VH + (nf * 8 + rowlane) * VSTRIDE + t * 32 +
                          poff16 + plo * (OFF_VL - OFF_VH));
                MMA_F16S(oacc[nf], pah[t], r4[0], r4[1]);
                MMA_F16S(oacc[nf], pah[t], r4[2], r4[3]);
            }
        }
        // no trailing sync — WAR protected by next iteration's leading sync
        cur = (cur == 2) ? 0 : cur + 1;
        nxt = (nxt == 2) ? 0 : nxt + 1;
    }

    // ---- epilogue: normalize, store fp16 hi only ----
    float inv0 = 1.0f / l0, inv1 = 1.0f / l1;
    int r0 = q0 + w * 16 + g;
#pragma unroll
    for (int nf = 0; nf < 16; ++nf) {
        int col = nf * 8 + 2 * q;
        {
            size_t off = (size_t)(b * S_ + r0) * DIM_ + h * HD_ + col;
            *(__half2*)(Oh + off) =
                __floats2half2_rn(oacc[nf][0] * inv0, oacc[nf][1] * inv0);
        }
        {
            size_t off = (size_t)(b * S_ + r0 + 8) * DIM_ + h * HD_ + col;
            *(__half2*)(Oh + off) =
                __floats2half2_rn(oacc[nf][2] * inv1, oacc[nf][3] * inv1);
        }
    }
}

// ============================================================================
// launch
// ============================================================================
extern "C" void kernel_launch(void* const* d_in, const int* in_sizes, int n_in,
                              void* d_out, int out_size)
{
    const float* x  = (const float*)d_in[0];
    const float* wq = (const float*)d_in[1];
    const float* wk = (const float*)d_in[2];
    const float* wv = (const float*)d_in[3];
    const float* wo = (const float*)d_in[4];
    const float* fc = (const float*)d_in[5];
    const float* fs = (const float*)d_in[6];
    float* out = (float*)d_out;

    __half *xh, *wbh, *woh, *ah;
    __half *qsh, *qsl, *ksh, *ksl, *vth, *vtl;
    cudaGetSymbolAddress((void**)&xh, g_xh);
    cudaGetSymbolAddress((void**)&wbh, g_wbh);
    cudaGetSymbolAddress((void**)&woh, g_woh);
    cudaGetSymbolAddress((void**)&ah, g_ah);
    cudaGetSymbolAddress((void**)&qsh, g_qsh); cudaGetSymbolAddress((void**)&qsl, g_qsl);
    cudaGetSymbolAddress((void**)&ksh, g_ksh); cudaGetSymbolAddress((void**)&ksl, g_ksl);
    cudaGetSymbolAddress((void**)&vth, g_vth); cudaGetSymbolAddress((void**)&vtl, g_vtl);

    const int GEMM_SMEM = 3 * STAGE_B;   // 110592
    cudaFuncSetAttribute(gemm_qkv, cudaFuncAttributeMaxDynamicSharedMemorySize,
                         GEMM_SMEM);
    cudaFuncSetAttribute(gemm_mma, cudaFuncAttributeMaxDynamicSharedMemorySize,
                         GEMM_SMEM);
    const int ATTN_SMEM = 3 * STG;       // 215040
    cudaFuncSetAttribute(attn_mma, cudaFuncAttributeMaxDynamicSharedMemorySize,
                         ATTN_SMEM);

    const int M = B_ * S_;               // 4096

    prep_all<<<dim3(128, 128, 5), dim3(32, 8)>>>(
        x, wq, wk, wv, wo, xh, wbh, woh);

    gemm_qkv<<<dim3(NQKV / 128, M / 128), 256, GEMM_SMEM>>>(
        xh, wbh, fc, fs, qsh, qsl, ksh, ksl, vth, vtl);

    attn_mma<<<dim3(S_ / 128, NH_, B_), 256, ATTN_SMEM>>>(
        qsh, qsl, ksh, ksl, vth, vtl, ah);

    gemm_mma<<<dim3(DIM_ / 128, M / 128), 256, GEMM_SMEM>>>(
        ah, woh, out, M, DIM_, DIM_);
}

// round 17
// speedup vs baseline: 1.1391x; 1.0799x over previous
#include <cuda_runtime.h>
#include <cuda_fp16.h>
#include <cstdint>
#include <cstddef>

#define B_   2
#define S_   2048
#define DIM_ 4096
#define NH_  32
#define NKV_ 8
#define HD_  128
#define NQKV (DIM_ + 2 * NKV_ * HD_)    // 6144

// ---------------- scratch (no allocations allowed) ----------------
__device__ __half g_xh[(size_t)B_ * S_ * DIM_];        // x fp16 (hi only)
__device__ __half g_wbh[(size_t)NQKV * DIM_];          // [wq;wk;wv] transposed hi
__device__ __half g_woh[(size_t)DIM_ * DIM_];          // wo transposed hi
__device__ __half g_ah[(size_t)B_ * S_ * DIM_];        // attention out (hi only)

__device__ __half g_qsh[(size_t)B_ * S_ * NH_ * HD_];  // post-rope Q (hi only)
__device__ __half g_ksh[(size_t)B_ * S_ * NKV_ * HD_]; // post-rope K hi/lo
__device__ __half g_ksl[(size_t)B_ * S_ * NKV_ * HD_];
__device__ __half g_vth[(size_t)B_ * NKV_ * HD_ * S_]; // V^T [b][kv][d][s] hi/lo
__device__ __half g_vtl[(size_t)B_ * NKV_ * HD_ * S_];

// ============================ PTX helpers (sm_80-portable) ============================
__device__ __forceinline__ uint32_t smem_u32(const void* p) {
    uint32_t a;
    asm("{ .reg .u64 t; cvta.to.shared.u64 t, %1; cvt.u32.u64 %0, t; }"
        : "=r"(a) : "l"(p));
    return a;
}

__device__ __forceinline__ void cp16(uint32_t dst, const void* src) {
    asm volatile("cp.async.cg.shared.global [%0], [%1], 16;" :: "r"(dst), "l"(src));
}

__device__ __forceinline__ void ldmx4(uint32_t* r, uint32_t addr) {
    asm volatile("ldmatrix.sync.aligned.m8n8.x4.shared.b16 {%0,%1,%2,%3}, [%4];"
        : "=r"(r[0]), "=r"(r[1]), "=r"(r[2]), "=r"(r[3]) : "r"(addr));
}

#define CP_COMMIT() asm volatile("cp.async.commit_group;" ::: "memory")
#define CP_WAIT1()  asm volatile("cp.async.wait_group 1;"  ::: "memory")
#define CP_WAIT0()  asm volatile("cp.async.wait_group 0;"  ::: "memory")

#define MMA_F16(c, A, Bf)                                                         \
    asm volatile(                                                                 \
        "mma.sync.aligned.m16n8k16.row.col.f32.f16.f16.f32 "                      \
        "{%0,%1,%2,%3},{%4,%5,%6,%7},{%8,%9},{%0,%1,%2,%3};"                      \
        : "+f"((c)[0]), "+f"((c)[1]), "+f"((c)[2]), "+f"((c)[3])                  \
        : "r"((A)[0]), "r"((A)[1]), "r"((A)[2]), "r"((A)[3]),                     \
          "r"((Bf)[0]), "r"((Bf)[1]))

#define MMA_F16S(c, A, b0, b1)                                                    \
    asm volatile(                                                                 \
        "mma.sync.aligned.m16n8k16.row.col.f32.f16.f16.f32 "                      \
        "{%0,%1,%2,%3},{%4,%5,%6,%7},{%8,%9},{%0,%1,%2,%3};"                      \
        : "+f"((c)[0]), "+f"((c)[1]), "+f"((c)[2]), "+f"((c)[3])                  \
        : "r"((A)[0]), "r"((A)[1]), "r"((A)[2]), "r"((A)[3]),                     \
          "r"(b0), "r"(b1))

// ============================================================================
// GEMM mainloop: C fp32 = Ah @ Bh^T  (single-pass fp16, weights hi-only)
// CTA 128x128, BK=64, 8 warps 2x4, ldmatrix, 2 CTAs/SM, 3-stage pipeline.
// ============================================================================
#define TILE_B   18432          // 128 x 144
#define STAGE_B  (2 * TILE_B)   // 36864

struct GemmCore {
    uint32_t sm0;
    int tid, lane, wid, wm, wn, q, rb;
    int row0, col0;
    const __half* src_[2];
    int K;

    __device__ __forceinline__ void init(char* sm,
        const __half* Ah, const __half* Bh, int K_) {
        sm0 = smem_u32(sm);
        tid = threadIdx.x; lane = tid & 31; wid = tid >> 5;
        wm = wid >> 2; wn = wid & 3; q = lane & 3; rb = lane >> 2;
        row0 = blockIdx.y * 128; col0 = blockIdx.x * 128;
        K = K_;
        src_[0] = Ah + (size_t)row0 * K;
        src_[1] = Bh + (size_t)col0 * K;
    }

    __device__ __forceinline__ void load_stage(int it, int s) {
        const uint32_t base = sm0 + s * STAGE_B;
        const int kel = it * 64;
#pragma unroll
        for (int t = 0; t < 2; ++t) {
            const __half* g = src_[t] + kel;
#pragma unroll
            for (int i = 0; i < 4; ++i) {
                int idx = tid + i * 256;
                int r = idx >> 3, kc = idx & 7;
                cp16(base + t * TILE_B + r * 144 + kc * 16,
                     g + (size_t)r * K + kc * 8);
            }
        }
        CP_COMMIT();
    }

    __device__ __forceinline__ void mainloop(float acc[4][4][4]) {
#pragma unroll
        for (int i = 0; i < 4; ++i)
#pragma unroll
            for (int j = 0; j < 4; ++j)
#pragma unroll
                for (int u = 0; u < 4; ++u) acc[i][j][u] = 0.f;

        const int KIT = K >> 6;
        load_stage(0, 0);
        load_stage(1, 1);

        const int a_row = lane & 15;
        const int a_off = (lane >> 4) * 16;
        const int b_row = (lane & 7) + (lane >> 4) * 8;
        const int b_off = ((lane >> 3) & 1) * 16;

        int cur = 0, nxt = 2;
        for (int it = 0; it < KIT; ++it) {
            if (it + 1 < KIT) { CP_WAIT1(); }
            else              { CP_WAIT0(); }
            __syncthreads();
            if (it + 2 < KIT) load_stage(it + 2, nxt);

            const uint32_t base = sm0 + cur * STAGE_B;
#pragma unroll
            for (int kk = 0; kk < 4; ++kk) {
                const int kb = kk * 32;
                uint32_t ah[4][4], bh[4][2];
#pragma unroll
                for (int mf = 0; mf < 4; ++mf)
                    ldmx4(ah[mf], base + (wm * 64 + mf * 16 + a_row) * 144 + kb + a_off);
#pragma unroll
                for (int np = 0; np < 2; ++np) {
                    uint32_t t4[4];
                    ldmx4(t4, base + TILE_B +
                              (wn * 32 + np * 16 + b_row) * 144 + kb + b_off);
                    bh[2*np][0] = t4[0]; bh[2*np][1] = t4[1];
                    bh[2*np+1][0] = t4[2]; bh[2*np+1][1] = t4[3];
                }
#pragma unroll
                for (int mf = 0; mf < 4; ++mf)
#pragma unroll
                    for (int nf = 0; nf < 4; ++nf)
                        MMA_F16(acc[mf][nf], ah[mf], bh[nf]);
            }
            cur = (cur == 2) ? 0 : cur + 1;
            nxt = (nxt == 2) ? 0 : nxt + 1;
        }
    }
};

// ---- RoPE + scale + fp16 split epilogue (WRITE_LO: also store residual) ----
template <bool WRITE_LO>
__device__ __forceinline__ void rope_epilogue(
    float acc[4][4][4], const GemmCore& gc, int colbase,
    const float* __restrict__ cs, const float* __restrict__ sn,
    __half* __restrict__ Oh, __half* __restrict__ Ol, int Nout, float scale)
{
#pragma unroll
    for (int mf = 0; mf < 4; ++mf) {
        int row = gc.row0 + gc.wm * 64 + mf * 16 + gc.rb;
        int s0 = row & (S_ - 1);
#pragma unroll
        for (int nf = 0; nf < 4; ++nf) {
            int col = colbase + gc.wn * 32 + nf * 8 + gc.q * 2;
            int p = (col & (HD_ - 1)) >> 1;
#pragma unroll
            for (int half = 0; half < 2; ++half) {
                int s = s0 + half * 8;
                float c = cs[(s << 6) + p];
                float si = sn[(s << 6) + p];
                float xr = acc[mf][nf][2 * half];
                float xi = acc[mf][nf][2 * half + 1];
                float o0 = fmaf(xr, c, -xi * si) * scale;
                float o1 = fmaf(xr, si,  xi * c) * scale;
                __half h0 = __float2half_rn(o0);
                __half h1 = __float2half_rn(o1);
                size_t off = (size_t)(row + half * 8) * Nout + col;
                *(__half2*)(Oh + off) = __halves2half2(h0, h1);
                if (WRITE_LO) {
                    *(__half2*)(Ol + off) = __halves2half2(
                        __float2half_rn(o0 - __half2float(h0)),
                        __float2half_rn(o1 - __half2float(h1)));
                }
            }
        }
    }
}

// ---- fused QKV projection: one GEMM over [6144,4096] weights ----
// Q: RoPE+scale, hi only.  K: RoPE, hi/lo.  V: hi/lo, transposed store.
__global__ __launch_bounds__(256, 2) void gemm_qkv(
    const __half* __restrict__ Ah, const __half* __restrict__ Bh,
    const float* __restrict__ cs, const float* __restrict__ sn,
    __half* __restrict__ qsh,
    __half* __restrict__ ksh, __half* __restrict__ ksl,
    __half* __restrict__ vth, __half* __restrict__ vtl)
{
    extern __shared__ __align__(16) char sm[];
    GemmCore gc; gc.init(sm, Ah, Bh, DIM_);
    float acc[4][4][4];
    gc.mainloop(acc);

    if (gc.col0 < DIM_) {
        rope_epilogue<false>(acc, gc, gc.col0, cs, sn, qsh, nullptr, DIM_,
                             0.08838834764831845f);
    } else if (gc.col0 < DIM_ + NKV_ * HD_) {
        rope_epilogue<true>(acc, gc, gc.col0 - DIM_, cs, sn, ksh, ksl,
                            NKV_ * HD_, 1.0f);
    } else {
        const int colbase = gc.col0 - (DIM_ + NKV_ * HD_);
#pragma unroll
        for (int mf = 0; mf < 4; ++mf) {
            int row = gc.row0 + gc.wm * 64 + mf * 16 + gc.rb;
            int b = row >> 11;
            int s = row & (S_ - 1);
#pragma unroll
            for (int nf = 0; nf < 4; ++nf) {
                int col = colbase + gc.wn * 32 + nf * 8 + gc.q * 2;
                int kv = col >> 7;
                int d  = col & (HD_ - 1);
                size_t base = ((size_t)(b * NKV_ + kv) * HD_ + d) * S_;
#pragma unroll
                for (int half = 0; half < 2; ++half) {
                    int ss = s + half * 8;
#pragma unroll
                    for (int e = 0; e < 2; ++e) {
                        float v = acc[mf][nf][2 * half + e];
                        __half hi = __float2half_rn(v);
                        size_t off = base + (size_t)e * S_ + ss;
                        vth[off] = hi;
                        vtl[off] = __float2half_rn(v - __half2float(hi));
                    }
                }
            }
        }
    }
}

// ---- plain GEMM: fp32 output (O projection) ----
__global__ __launch_bounds__(256, 2) void gemm_mma(
    const __half* __restrict__ Ah, const __half* __restrict__ Bh,
    float* __restrict__ C, int M, int N, int K)
{
    extern __shared__ __align__(16) char sm[];
    GemmCore gc; gc.init(sm, Ah, Bh, K);
    float acc[4][4][4];
    gc.mainloop(acc);
#pragma unroll
    for (int mf = 0; mf < 4; ++mf) {
        int row = gc.row0 + gc.wm * 64 + mf * 16 + gc.rb;
#pragma unroll
        for (int nf = 0; nf < 4; ++nf) {
            int col = gc.col0 + gc.wn * 32 + nf * 8 + gc.q * 2;
            *(float2*)(C + (size_t)row * N + col) =
                make_float2(acc[mf][nf][0], acc[mf][nf][1]);
            *(float2*)(C + (size_t)(row + 8) * N + col) =
                make_float2(acc[mf][nf][2], acc[mf][nf][3]);
        }
    }
}

// ============================================================================
// Fused prep: z=0 wq, z=1 wk, z=2 wv (combined buffer), z=3 wo, z=4 x->fp16
// ============================================================================
__global__ __launch_bounds__(256) void prep_all(
    const float* __restrict__ x,
    const float* __restrict__ wq, const float* __restrict__ wk,
    const float* __restrict__ wv, const float* __restrict__ wo,
    __half* __restrict__ xh,
    __half* __restrict__ wbh, __half* __restrict__ woh)
{
    const int z = blockIdx.z;
    const int tx = threadIdx.x, ty = threadIdx.y;

    if (z == 4) {
        int i = (blockIdx.y * 128 + blockIdx.x) * 256 + ty * 32 + tx;
        float4 v = ((const float4*)x)[i];
        ((__half2*)xh)[2 * i + 0] = __floats2half2_rn(v.x, v.y);
        ((__half2*)xh)[2 * i + 1] = __floats2half2_rn(v.z, v.w);
        return;
    }

    const float* w; __half* th; int N; int rowbase;
    switch (z) {
        case 0: w = wq; th = wbh; N = DIM_;        rowbase = 0;     break;
        case 1: w = wk; th = wbh; N = NKV_ * HD_;  rowbase = DIM_;  break;
        case 2: w = wv; th = wbh; N = NKV_ * HD_;  rowbase = DIM_ + NKV_ * HD_; break;
        default: w = wo; th = woh; N = DIM_;       rowbase = 0;     break;
    }
    const int K = DIM_;
    int n0 = blockIdx.x * 32, k0 = blockIdx.y * 32;
    if (n0 >= N) return;

    __shared__ float s[32][33];
#pragma unroll
    for (int i = ty; i < 32; i += 8)
        s[i][tx] = w[(size_t)(k0 + i) * N + n0 + tx];
    __syncthreads();
#pragma unroll
    for (int i = ty; i < 32; i += 8)
        th[(size_t)(rowbase + n0 + i) * K + k0 + tx] = __float2half_rn(s[tx][i]);
}

// ============================================================================
// Tensor-core flash attention (fp16, 2-pass QK (Qh*Kh + Qh*Kl), 2-pass PV,
// ldmatrix, 3-stage cp.async pipeline, single sync per k-block).
// ============================================================================
#define AK       64
#define NKB      (S_ / AK)
#define KSTRIDE  272
#define VSTRIDE  144
#define OFF_KL   17408
#define OFF_VH   34816
#define OFF_VL   53248
#define STG      71680

__global__ __launch_bounds__(256, 1) void attn_mma(
    const __half* __restrict__ Qh,
    const __half* __restrict__ Kh, const __half* __restrict__ Kl,
    const __half* __restrict__ Vh, const __half* __restrict__ Vl,
    __half* __restrict__ Oh)
{
    extern __shared__ __align__(16) char sm[];
    const uint32_t sm0 = smem_u32(sm);
    const int tid = threadIdx.x, lane = tid & 31, w = tid >> 5;
    const int g = lane >> 2, q = lane & 3;
    const int q0 = blockIdx.x * 128;
    const int h = blockIdx.y, b = blockIdx.z;
    const int kvh = h >> 2;

    const int rowlane = lane & 7;
    const int part = lane >> 3;
    const int poff16 = (part & 1) * 16;
    const int plo = part >> 1;

    // ---- stage Q (hi only) through smem, build register fragments ----
    uint32_t fqh[8][4];
    {
#pragma unroll
        for (int i = 0; i < 8; ++i) {
            int c = tid + i * 256;
            int r = c >> 4, cc = c & 15;
            cp16(sm0 + r * KSTRIDE + cc * 16,
                 Qh + ((size_t)((b * S_ + q0 + r) * NH_) + h) * HD_ + cc * 8);
        }
        CP_COMMIT(); CP_WAIT0();
        __syncthreads();
        uint32_t base = sm0 + (w * 16 + (lane & 15)) * KSTRIDE + (lane >> 4) * 16;
#pragma unroll
        for (int t = 0; t < 8; ++t)
            ldmx4(fqh[t], base + t * 32);
        __syncthreads();
    }

    auto prefetch = [&](int kb, int s) {
        uint32_t st = sm0 + s * STG;
#pragma unroll
        for (int i = 0; i < 4; ++i) {
            int c = tid + i * 256;
            int r = c >> 4, cc = c & 15;
            size_t go = ((size_t)((b * S_ + kb * AK + r) * NKV_) + kvh) * HD_ + cc * 8;
            cp16(st + r * KSTRIDE + cc * 16, Kh + go);
            cp16(st + OFF_KL + r * KSTRIDE + cc * 16, Kl + go);
        }
#pragma unroll
        for (int i = 0; i < 4; ++i) {
            int c = tid + i * 256;
            int d = c >> 3, cc = c & 7;
            size_t go = ((size_t)(b * NKV_ + kvh) * HD_ + d) * S_ + kb * AK + cc * 8;
            cp16(st + OFF_VH + d * VSTRIDE + cc * 16, Vh + go);
            cp16(st + OFF_VL + d * VSTRIDE + cc * 16, Vl + go);
        }
        CP_COMMIT();
    };

    float oacc[16][4];
#pragma unroll
    for (int i = 0; i < 16; ++i)
#pragma unroll
        for (int u = 0; u < 4; ++u) oacc[i][u] = 0.f;
    float m0 = -1e30f, m1 = -1e30f, l0 = 0.f, l1 = 0.f;

    prefetch(0, 0);
    prefetch(1, 1);

    int cur = 0, nxt = 2;
    for (int kb = 0; kb < NKB; ++kb) {
        if (kb + 1 < NKB) { CP_WAIT1(); }
        else              { CP_WAIT0(); }
        __syncthreads();
        if (kb + 2 < NKB) prefetch(kb + 2, nxt);

        const uint32_t st = sm0 + cur * STG;

        // ---- S = Qh*(Kh+Kl) (2-pass, f32 acc) ----
        float sacc[8][4];
#pragma unroll
        for (int n = 0; n < 8; ++n)
#pragma unroll
            for (int u = 0; u < 4; ++u) sacc[n][u] = 0.f;

#pragma unroll
        for (int t = 0; t < 8; ++t) {
#pragma unroll
            for (int n = 0; n < 8; ++n) {
                uint32_t r4[4];
                ldmx4(r4, st + (n * 8 + rowlane) * KSTRIDE + t * 32 + poff16 +
                          plo * OFF_KL);
                MMA_F16S(sacc[n], fqh[t], r4[0], r4[1]);
                MMA_F16S(sacc[n], fqh[t], r4[2], r4[3]);
            }
        }

        // ---- online softmax ----
        float rmax0 = -1e30f, rmax1 = -1e30f;
#pragma unroll
        for (int n = 0; n < 8; ++n) {
            rmax0 = fmaxf(rmax0, fmaxf(sacc[n][0], sacc[n][1]));
            rmax1 = fmaxf(rmax1, fmaxf(sacc[n][2], sacc[n][3]));
        }
        rmax0 = fmaxf(rmax0, __shfl_xor_sync(0xffffffffu, rmax0, 1));
        rmax0 = fmaxf(rmax0, __shfl_xor_sync(0xffffffffu, rmax0, 2));
        rmax1 = fmaxf(rmax1, __shfl_xor_sync(0xffffffffu, rmax1, 1));
        rmax1 = fmaxf(rmax1, __shfl_xor_sync(0xffffffffu, rmax1, 2));

        float nm0 = fmaxf(m0, rmax0), nm1 = fmaxf(m1, rmax1);
        float f0 = __expf(m0 - nm0),  f1 = __expf(m1 - nm1);
        m0 = nm0; m1 = nm1;

        float sum0 = 0.f, sum1 = 0.f;
#pragma unroll
        for (int n = 0; n < 8; ++n) {
            float p0 = __expf(sacc[n][0] - nm0);
            float p1 = __expf(sacc[n][1] - nm0);
            float p2 = __expf(sacc[n][2] - nm1);
            float p3 = __expf(sacc[n][3] - nm1);
            sum0 += p0 + p1; sum1 += p2 + p3;
            sacc[n][0] = p0; sacc[n][1] = p1; sacc[n][2] = p2; sacc[n][3] = p3;
        }
        sum0 += __shfl_xor_sync(0xffffffffu, sum0, 1);
        sum0 += __shfl_xor_sync(0xffffffffu, sum0, 2);
        sum1 += __shfl_xor_sync(0xffffffffu, sum1, 1);
        sum1 += __shfl_xor_sync(0xffffffffu, sum1, 2);
        l0 = l0 * f0 + sum0;
        l1 = l1 * f1 + sum1;

        // P -> hi A fragments (register repack)
        uint32_t pah[4][4];
#pragma unroll
        for (int t = 0; t < 4; ++t) {
#pragma unroll
            for (int hw = 0; hw < 2; ++hw) {
                const float* pv = sacc[2 * t + hw];
#pragma unroll
                for (int uu = 0; uu < 2; ++uu) {
                    __half2 hp = __floats2half2_rn(pv[2 * uu], pv[2 * uu + 1]);
                    pah[t][hw * 2 + uu] = *(uint32_t*)&hp;
                }
            }
        }

#pragma unroll
        for (int nf = 0; nf < 16; ++nf) {
            oacc[nf][0] *= f0; oacc[nf][1] *= f0;
            oacc[nf][2] *= f1; oacc[nf][3] *= f1;
        }

        // ---- O += Ph*(Vh+Vl)  (2-pass PV, f32 acc) ----
#pragma unroll
        for (int t = 0; t < 4; ++t) {
#pragma unroll
            for (int nf = 0; nf < 16; ++nf) {
                uint32_t r4[4];
                ldmx4(r4, st + OFF_VH + (nf * 8 + rowlane) * VSTRIDE + t * 32 +
                          poff16 + plo * (OFF_VL - OFF_VH));
                MMA_F16S(oacc[nf], pah[t], r4[0], r4[1]);
                MMA_F16S(oacc[nf], pah[t], r4[2], r4[3]);
            }
        }
        cur = (cur == 2) ? 0 : cur + 1;
        nxt = (nxt == 2) ? 0 : nxt + 1;
    }

    // ---- epilogue: normalize, store fp16 hi only ----
    float inv0 = 1.0f / l0, inv1 = 1.0f / l1;
    int r0 = q0 + w * 16 + g;
#pragma unroll
    for (int nf = 0; nf < 16; ++nf) {
        int col = nf * 8 + 2 * q;
        {
            size_t off = (size_t)(b * S_ + r0) * DIM_ + h * HD_ + col;
            *(__half2*)(Oh + off) =
                __floats2half2_rn(oacc[nf][0] * inv0, oacc[nf][1] * inv0);
        }
        {
            size_t off = (size_t)(b * S_ + r0 + 8) * DIM_ + h * HD_ + col;
            *(__half2*)(Oh + off) =
                __floats2half2_rn(oacc[nf][2] * inv1, oacc[nf][3] * inv1);
        }
    }
}

// ============================================================================
// launch
// ============================================================================
extern "C" void kernel_launch(void* const* d_in, const int* in_sizes, int n_in,
                              void* d_out, int out_size)
{
    const float* x  = (const float*)d_in[0];
    const float* wq = (const float*)d_in[1];
    const float* wk = (const float*)d_in[2];
    const float* wv = (const float*)d_in[3];
    const float* wo = (const float*)d_in[4];
    const float* fc = (const float*)d_in[5];
    const float* fs = (const float*)d_in[6];
    float* out = (float*)d_out;

    __half *xh, *wbh, *woh, *ah;
    __half *qsh, *ksh, *ksl, *vth, *vtl;
    cudaGetSymbolAddress((void**)&xh, g_xh);
    cudaGetSymbolAddress((void**)&wbh, g_wbh);
    cudaGetSymbolAddress((void**)&woh, g_woh);
    cudaGetSymbolAddress((void**)&ah, g_ah);
    cudaGetSymbolAddress((void**)&qsh, g_qsh);
    cudaGetSymbolAddress((void**)&ksh, g_ksh); cudaGetSymbolAddress((void**)&ksl, g_ksl);
    cudaGetSymbolAddress((void**)&vth, g_vth); cudaGetSymbolAddress((void**)&vtl, g_vtl);

    const int GEMM_SMEM = 3 * STAGE_B;   // 110592
    cudaFuncSetAttribute(gemm_qkv, cudaFuncAttributeMaxDynamicSharedMemorySize,
                         GEMM_SMEM);
    cudaFuncSetAttribute(gemm_mma, cudaFuncAttributeMaxDynamicSharedMemorySize,
                         GEMM_SMEM);
    const int ATTN_SMEM = 3 * STG;       // 215040
    cudaFuncSetAttribute(attn_mma, cudaFuncAttributeMaxDynamicSharedMemorySize,
                         ATTN_SMEM);

    const int M = B_ * S_;               // 4096

    prep_all<<<dim3(128, 128, 5), dim3(32, 8)>>>(
        x, wq, wk, wv, wo, xh, wbh, woh);

    gemm_qkv<<<dim3(NQKV / 128, M / 128), 256, GEMM_SMEM>>>(
        xh, wbh, fc, fs, qsh, ksh, ksl, vth, vtl);

    attn_mma<<<dim3(S_ / 128, NH_, B_), 256, ATTN_SMEM>>>(
        qsh, ksh, ksl, vth, vtl, ah);

    gemm_mma<<<dim3(DIM_ / 128, M / 128), 256, GEMM_SMEM>>>(
        ah, woh, out, M, DIM_, DIM_);
}